// round 17
// baseline (speedup 1.0000x reference)
#include <cuda_runtime.h>
#include <cuda_bf16.h>
#include <cstdint>

#define T_LEN 16384
#define HID   128
#define G4    512   // 4*HID gate rows

// ---------------- scratch (static device globals; no allocation) -------------
// gx layout: [t][unit 0..127][i,g,f,o]  (pos = ((gate&1)<<1)|(gate>>1))
__device__ __align__(16) float g_gx[4u * T_LEN * G4];   // [l0f,l0b,l1f,l1b]
__device__ __align__(16) float g_h0[T_LEN * 2 * HID];   // layer0 out [t][256]
__device__ __align__(16) float g_h1[T_LEN * 2 * HID];   // layer1 out [t][256]

// ---------------- helpers ----------------------------------------------------
__device__ __forceinline__ void fma2(unsigned long long& d,
                                     unsigned long long a,
                                     unsigned long long b) {
    asm("fma.rn.f32x2 %0, %1, %2, %0;" : "+l"(d) : "l"(a), "l"(b));
}
__device__ __forceinline__ float unpack_sum(unsigned long long v) {
    float lo, hi;
    asm("mov.b64 {%0,%1}, %2;" : "=f"(lo), "=f"(hi) : "l"(v));
    return lo + hi;
}

// ---------------- kernel 1: layer-0 input projection (IN=1) ------------------
__global__ void k_gx0(const float* __restrict__ x,
                      const float* __restrict__ wf, const float* __restrict__ bfi,
                      const float* __restrict__ bfh,
                      const float* __restrict__ wb, const float* __restrict__ bbi,
                      const float* __restrict__ bbh,
                      float* __restrict__ gxf, float* __restrict__ gxb) {
    unsigned idx = blockIdx.x * 256u + threadIdx.x;
    if (idx >= (unsigned)T_LEN * G4) return;
    unsigned t = idx >> 9, r = idx & 511u;             // r = gate*128 + unit
    unsigned gate = r >> 7;
    unsigned pos  = ((gate & 1u) << 1) | (gate >> 1);  // i,g,f,o order
    unsigned dst = t * G4 + (r & 127u) * 4u + pos;
    float xv = x[t];
    gxf[dst] = xv * wf[r] + bfi[r] + bfh[r];
    gxb[dst] = xv * wb[r] + bbi[r] + bbh[r];
}

// ---------------- kernel 2: SINGLE-SM scan, 256 threads, 224 RF wts ----------
// Grid = 2 CTAs (dir 0 fwd, 1 bwd), 256 threads each.
// Warp w (0..7), lane l: unit u = w*16 + (l>>1), k-half e = l&1 (k[e*64..+64)).
// Per thread: 4 gates x 64 k. Weights: k-sub[0..55] per gate in RF (224 regs,
// 14 ull2/gate); k-sub[56..63] streamed from smem (8 LDS.128/thread, 32KB/step
// = 256 wf). h: 16 ull2 broadcast reads (128 wf). FMA floor (512cyc) binds.
// 4 accumulators (one per gate). Combine halves: 4 shfl; lane activates its
// 2 gates (gx pre-permuted so lane e loads float2 {own gates}); 2 shfl hand
// f,o to writer (e==0); one __syncthreads per step.
__global__ void __launch_bounds__(256, 1)
k_lstm1(const float* __restrict__ gx_f, const float* __restrict__ gx_b,
        const float* __restrict__ whh_f, const float* __restrict__ whh_b,
        float* __restrict__ hcat) {
    __shared__ ulonglong2 ws[8 * 256];           // [g*2+c][256 tid] = 32KB
    __shared__ float hbuf[2 * 136 + 8];          // half e at e*68 per buffer

    const int dir = blockIdx.x;
    const float* gx  = dir ? gx_b  : gx_f;
    const float* whh = dir ? whh_b : whh_f;

    const int tid = threadIdx.x;
    const int l   = tid & 31;
    const int u   = (tid >> 5) * 16 + (l >> 1);  // unit 0..127
    const int e   = l & 1;                       // k-half
    const bool wr = (e == 0);

    // ---- stage weights: RF k-sub[0..55] per gate; smem k-sub[56..63] --------
    ulonglong2 wv[4][14];                        // 224 regs
    ulonglong2* wsp = ws + tid;
#pragma unroll
    for (int g = 0; g < 4; g++) {
        const ulonglong2* row = (const ulonglong2*)
            (whh + (size_t)(g * HID + u) * HID + e * 64);
#pragma unroll
        for (int i = 0; i < 14; i++) wv[g][i] = row[i];
        wsp[(g * 2 + 0) * 256] = row[14];
        wsp[(g * 2 + 1) * 256] = row[15];
    }
    for (int i = tid; i < 272; i += 256) hbuf[i] = 0.f;
    __syncthreads();

    float c = 0.f;
    const int t_first = dir ? (T_LEN - 1) : 0;
    const float* gx2p = gx + (size_t)0;          // base
    float2 gx_next = *(const float2*)(gx + (size_t)t_first * G4 + u * 4 + e * 2);

    for (int s = 0; s < T_LEN; ++s) {
        const int t  = dir ? (T_LEN - 1 - s) : s;
        const int rd = (s & 1) ^ 1;              // buffer holding h(s-1)
        const int sb = s & 1;
        const float2 gxv = gx_next;

        {   // prefetch next step's gx
            int t2 = dir ? (t - 1) : (t + 1);
            if (s == T_LEN - 1) t2 = t;
            gx_next = *(const float2*)(gx2p + (size_t)t2 * G4 + u * 4 + e * 2);
        }

        const ulonglong2* hb2 =
            (const ulonglong2*)(hbuf + rd * 136 + e * 68);

        // ---- RF portion: k-sub[0..55], 4 accumulators ----------------------
        unsigned long long a0 = 0ull, a1 = 0ull, a2 = 0ull, a3 = 0ull;
#pragma unroll
        for (int i = 0; i < 14; i++) {
            ulonglong2 hv = hb2[i];
            fma2(a0, wv[0][i].x, hv.x); fma2(a0, wv[0][i].y, hv.y);
            fma2(a1, wv[1][i].x, hv.x); fma2(a1, wv[1][i].y, hv.y);
            fma2(a2, wv[2][i].x, hv.x); fma2(a2, wv[2][i].y, hv.y);
            fma2(a3, wv[3][i].x, hv.x); fma2(a3, wv[3][i].y, hv.y);
        }
        // ---- smem portion: k-sub[56..63] -----------------------------------
#pragma unroll
        for (int cc = 0; cc < 2; cc++) {
            ulonglong2 hv = hb2[14 + cc];
            ulonglong2 w0 = wsp[(0 * 2 + cc) * 256];
            ulonglong2 w1 = wsp[(1 * 2 + cc) * 256];
            ulonglong2 w2 = wsp[(2 * 2 + cc) * 256];
            ulonglong2 w3 = wsp[(3 * 2 + cc) * 256];
            fma2(a0, w0.x, hv.x); fma2(a0, w0.y, hv.y);
            fma2(a1, w1.x, hv.x); fma2(a1, w1.y, hv.y);
            fma2(a2, w2.x, hv.x); fma2(a2, w2.y, hv.y);
            fma2(a3, w3.x, hv.x); fma2(a3, w3.y, hv.y);
        }

        float S0 = unpack_sum(a0);               // i partial (this k-half)
        float S1 = unpack_sum(a1);               // f
        float S2 = unpack_sum(a2);               // g
        float S3 = unpack_sum(a3);               // o

        // ---- combine k-halves: 4 independent shfls -------------------------
        S0 += __shfl_xor_sync(0xFFFFFFFFu, S0, 1);
        S1 += __shfl_xor_sync(0xFFFFFFFFu, S1, 1);
        S2 += __shfl_xor_sync(0xFFFFFFFFu, S2, 1);
        S3 += __shfl_xor_sync(0xFFFFFFFFu, S3, 1);

        // ---- lane0 activates {i,g}, lane1 {f,o} (gx pre-permuted) ----------
        float x1 = (wr ? S0 : S1) + gxv.x;             // sigmoid both lanes
        float x2 = (wr ? S2 : S3) + gxv.y;             // tanh on lane0 only
        float ex1 = __expf(x1);
        float th1 = 1.f - __fdividef(2.f, ex1 + 1.f);  // tanh(x1/2)
        float r1  = 0.5f + 0.5f * th1;                 // sigmoid(x1)
        float ag2 = wr ? (2.f * x2) : x2;
        float ex2 = __expf(ag2);
        float th2 = 1.f - __fdividef(2.f, ex2 + 1.f);
        float r2  = wr ? th2 : (0.5f + 0.5f * th2);

        // ---- hand f,o to writer lane ---------------------------------------
        float fv = __shfl_xor_sync(0xFFFFFFFFu, r1, 1);
        float ov = __shfl_xor_sync(0xFFFFFFFFu, r2, 1);

        if (wr) {
            c = fv * c + r1 * r2;                // i * g
            float exc = __expf(2.f * c);
            float thc = 1.f - __fdividef(2.f, exc + 1.f);
            float h = ov * thc;
            hbuf[sb * 136 + u + (u >> 6) * 4] = h;   // pad at 64-boundary
            hcat[(size_t)t * (2 * HID) + dir * HID + u] = h;
        }
        __syncthreads();                          // h(s) visible, WAR safe
    }
}

// ---------------- kernel 3: layer-1 input projection GEMM --------------------
__global__ void __launch_bounds__(512)
k_gx1(const float* __restrict__ h0,
      const float* __restrict__ Wf, const float* __restrict__ bfi,
      const float* __restrict__ bfh,
      const float* __restrict__ Wb, const float* __restrict__ bbi,
      const float* __restrict__ bbh,
      float* __restrict__ gxf, float* __restrict__ gxb) {
    const int dir = blockIdx.y;
    const float* W  = dir ? Wb  : Wf;
    const float* bi = dir ? bbi : bfi;
    const float* bh = dir ? bbh : bfh;
    float* gx       = dir ? gxb : gxf;

    __shared__ float hs[32 * 256];
    const int t0 = blockIdx.x * 32;
    const int r  = threadIdx.x;                        // gate*128 + unit

    for (int idx = r; idx < 32 * 256; idx += 512)
        hs[idx] = h0[(size_t)t0 * 256 + idx];
    __syncthreads();

    float acc[32];
    const float bias = bi[r] + bh[r];
#pragma unroll
    for (int tt = 0; tt < 32; tt++) acc[tt] = bias;

    const float4* wrow = (const float4*)(W + (size_t)r * 256);
    for (int k4 = 0; k4 < 64; k4++) {
        float4 w4 = wrow[k4];
#pragma unroll
        for (int tt = 0; tt < 32; tt++) {
            float4 hv = *(const float4*)(hs + tt * 256 + k4 * 4);
            acc[tt] += w4.x * hv.x + w4.y * hv.y + w4.z * hv.z + w4.w * hv.w;
        }
    }
    const unsigned gate = r >> 7;
    const unsigned pos  = ((gate & 1u) << 1) | (gate >> 1);
    const unsigned dst_r = (r & 127u) * 4u + pos;      // [unit][i,g,f,o]
#pragma unroll
    for (int tt = 0; tt < 32; tt++)
        gx[(size_t)(t0 + tt) * G4 + dst_r] = acc[tt];
}

// ---------------- kernel 4: FC head ------------------------------------------
__global__ void __launch_bounds__(128)
k_head(const float* __restrict__ h1,
       const float* __restrict__ fc1w, const float* __restrict__ fc1b,
       const float* __restrict__ fc2w, const float* __restrict__ fc2b,
       float* __restrict__ out) {
    __shared__ float hs[8 * 256];
    __shared__ float z[8 * 128];
    const int t0 = blockIdx.x * 8;
    const int j  = threadIdx.x;

    for (int idx = j; idx < 8 * 256; idx += 128)
        hs[idx] = h1[(size_t)t0 * 256 + idx];
    __syncthreads();

    float acc[8];
    const float b = fc1b[j];
#pragma unroll
    for (int tt = 0; tt < 8; tt++) acc[tt] = b;

    const float4* wrow = (const float4*)(fc1w + (size_t)j * 256);
    for (int k4 = 0; k4 < 64; k4++) {
        float4 w4 = wrow[k4];
#pragma unroll
        for (int tt = 0; tt < 8; tt++) {
            float4 hv = *(const float4*)(hs + tt * 256 + k4 * 4);
            acc[tt] += w4.x * hv.x + w4.y * hv.y + w4.z * hv.z + w4.w * hv.w;
        }
    }
#pragma unroll
    for (int tt = 0; tt < 8; tt++) {
        float a = acc[tt];
        z[tt * 128 + j] = a > 0.f ? a : 0.01f * a;
    }
    __syncthreads();

    const int wid  = j >> 5;
    const int lane = j & 31;
#pragma unroll
    for (int q = 0; q < 2; q++) {
        int tt = wid * 2 + q;
        const float* zz = z + tt * 128;
        float s = fc2w[lane]      * zz[lane]
                + fc2w[lane + 32] * zz[lane + 32]
                + fc2w[lane + 64] * zz[lane + 64]
                + fc2w[lane + 96] * zz[lane + 96];
#pragma unroll
        for (int off = 16; off > 0; off >>= 1)
            s += __shfl_down_sync(0xFFFFFFFFu, s, off);
        if (lane == 0)
            out[t0 + tt] = s + fc2b[0];
    }
}

// ---------------- launcher ---------------------------------------------------
extern "C" void kernel_launch(void* const* d_in, const int* in_sizes, int n_in,
                              void* d_out, int out_size) {
    const float* x        = (const float*)d_in[0];
    const float* w_ih_l0  = (const float*)d_in[1];
    const float* w_hh_l0  = (const float*)d_in[2];
    const float* b_ih_l0  = (const float*)d_in[3];
    const float* b_hh_l0  = (const float*)d_in[4];
    const float* w_ih_l0r = (const float*)d_in[5];
    const float* w_hh_l0r = (const float*)d_in[6];
    const float* b_ih_l0r = (const float*)d_in[7];
    const float* b_hh_l0r = (const float*)d_in[8];
    const float* w_ih_l1  = (const float*)d_in[9];
    const float* w_hh_l1  = (const float*)d_in[10];
    const float* b_ih_l1  = (const float*)d_in[11];
    const float* b_hh_l1  = (const float*)d_in[12];
    const float* w_ih_l1r = (const float*)d_in[13];
    const float* w_hh_l1r = (const float*)d_in[14];
    const float* b_ih_l1r = (const float*)d_in[15];
    const float* b_hh_l1r = (const float*)d_in[16];
    const float* fc1_w    = (const float*)d_in[17];
    const float* fc1_b    = (const float*)d_in[18];
    const float* fc2_w    = (const float*)d_in[19];
    const float* fc2_b    = (const float*)d_in[20];
    float* out = (float*)d_out;

    float *gx_base, *h0, *h1;
    cudaGetSymbolAddress((void**)&gx_base, g_gx);
    cudaGetSymbolAddress((void**)&h0, g_h0);
    cudaGetSymbolAddress((void**)&h1, g_h1);
    float* gx0f = gx_base;
    float* gx0b = gx_base + (size_t)1 * T_LEN * G4;
    float* gx1f = gx_base + (size_t)2 * T_LEN * G4;
    float* gx1b = gx_base + (size_t)3 * T_LEN * G4;

    k_gx0<<<(T_LEN * G4 + 255) / 256, 256>>>(x, w_ih_l0, b_ih_l0, b_hh_l0,
                                             w_ih_l0r, b_ih_l0r, b_hh_l0r,
                                             gx0f, gx0b);
    k_lstm1<<<2, 256>>>(gx0f, gx0b, w_hh_l0, w_hh_l0r, h0);
    k_gx1<<<dim3(T_LEN / 32, 2), 512>>>(h0, w_ih_l1, b_ih_l1, b_hh_l1,
                                        w_ih_l1r, b_ih_l1r, b_hh_l1r,
                                        gx1f, gx1b);
    k_lstm1<<<2, 256>>>(gx1f, gx1b, w_hh_l1, w_hh_l1r, h1);
    k_head<<<T_LEN / 8, 128>>>(h1, fc1_w, fc1_b, fc2_w, fc2_b, out);
}